// round 8
// baseline (speedup 1.0000x reference)
#include <cuda_runtime.h>
#include <math.h>
#include <stdint.h>

#define BB 2
#define SS 1024
#define EE 512
#define HH 64
#define DKK 8
#define FF 2048
#define BS (BB*SS)   // 2048

// ---- scratch (device globals: allocation-free) ----
__device__ float g_q[BB*HH*SS*DKK];   // [B][H][S][8]
__device__ float g_attn[BS*EE];
__device__ float g_x1[BS*EE];
__device__ float g_qf[BS*EE];
__device__ float g_hdn[BS*FF];
__device__ float g_pre[BS*EE];

__device__ __forceinline__ float ex2a(float x) {
    float r; asm("ex2.approx.f32 %0, %1;" : "=f"(r) : "f"(x)); return r;
}
// deg-4 range-reduced exp2 on the FMA pipe (rel err ~4e-5), t in [-4.2, 4.2]
__device__ __forceinline__ float exp2p(float t) {
    float tm = t + 12582912.0f;              // round-to-nearest via magic
    float f  = t - (tm - 12582912.0f);       // f in [-0.5, 0.5]
    float p  = 1.0f + f*(0.69314718f + f*(0.24022652f + f*(0.05550411f
             + f*0.00961813f)));
    return __int_as_float(__float_as_int(p) + (__float_as_int(tm) << 23));
}

// m16n8k8 tf32 mma (HW truncates f32 regs to tf32)
__device__ __forceinline__ void mma_tf32(float* acc, float a0, float a1,
                                         float a2, float a3, float b0, float b1) {
    uint32_t A0 = __float_as_uint(a0), A1 = __float_as_uint(a1);
    uint32_t A2 = __float_as_uint(a2), A3 = __float_as_uint(a3);
    uint32_t B0 = __float_as_uint(b0), B1 = __float_as_uint(b1);
    asm volatile(
        "mma.sync.aligned.m16n8k8.row.col.f32.tf32.tf32.f32 "
        "{%0,%1,%2,%3},{%4,%5,%6,%7},{%8,%9},{%0,%1,%2,%3};"
        : "+f"(acc[0]), "+f"(acc[1]), "+f"(acc[2]), "+f"(acc[3])
        : "r"(A0), "r"(A1), "r"(A2), "r"(A3), "r"(B0), "r"(B1));
}
__device__ __forceinline__ void mma_tf32u(float& c0, float& c1, float& c2, float& c3,
                                          uint32_t A0, uint32_t A1, uint32_t A2, uint32_t A3,
                                          uint32_t B0, uint32_t B1) {
    asm volatile(
        "mma.sync.aligned.m16n8k8.row.col.f32.tf32.tf32.f32 "
        "{%0,%1,%2,%3},{%4,%5,%6,%7},{%8,%9},{%0,%1,%2,%3};"
        : "+f"(c0), "+f"(c1), "+f"(c2), "+f"(c3)
        : "r"(A0), "r"(A1), "r"(A2), "r"(A3), "r"(B0), "r"(B1));
}

// =====================================================================
// K1: ring expvals
// =====================================================================
__global__ void qkv_kernel(const float* __restrict__ x,
                           const float* __restrict__ theta) {
    int i = blockIdx.x * 256 + threadIdx.x;
    int h  = i & (HH-1);
    int bs = i >> 6;
    const float* xp = x + bs*EE + h*DKK;
    float4 xa = *(const float4*)xp;
    float4 xb = *(const float4*)(xp + 4);
    float c0 = __cosf(xa.x + theta[0]);
    float c1 = __cosf(xa.y + theta[1]);
    float c2 = __cosf(xa.z + theta[2]);
    float c3 = __cosf(xa.w + theta[3]);
    float c4 = __cosf(xb.x + theta[4]);
    float c5 = __cosf(xb.y + theta[5]);
    float c6 = __cosf(xb.z + theta[6]);
    float c7 = __cosf(xb.w + theta[7]);
    float o1 = c0*c1;
    float o2 = o1*c2;
    float o3 = o2*c3;
    float o4 = o3*c4;
    float o5 = o4*c5;
    float o6 = o5*c6;
    float o7 = o6*c7;
    float o0 = c1*c2*c3*c4*c5*c6*c7;
    int b = bs >> 10, s = bs & (SS-1);
    float* qp = g_q + (((b*HH + h)*SS) + s)*DKK;
    *(float4*)qp       = make_float4(o0, o1, o2, o3);
    *(float4*)(qp + 4) = make_float4(o4, o5, o6, o7);
}

// =====================================================================
// K2: tensor-core attention, zero-shuffle, 32 rows/warp.
// Two 16-row MMA tiles per warp share every B-fragment (halves LDS/issue).
// Token-permuted scores B operand (sigma(g)) puts the scores accumulator
// directly in AV A-fragment layout.
// exp split across pipes: tile0 via MUFU ex2, tile1 via FMA-pipe poly —
// MUFU was the measured binder (R6 neutrality diagnosis).
// =====================================================================
__global__ void __launch_bounds__(256, 4) attn_mma_kernel() {
    __shared__ float Ks[SS*12];       // 48 KB, row stride 12
    const int bh   = blockIdx.x >> 2;
    const int tile = blockIdx.x & 3;  // 4 tiles of 256 rows

    const float* qsrc = g_q + bh*(SS*DKK);
    for (int j = threadIdx.x; j < SS*DKK/4; j += 256) {
        float4 v = ((const float4*)qsrc)[j];
        int t = j >> 1, hf = (j & 1) * 4;
        *(float4*)&Ks[t*12 + hf] = v;
    }
    __syncthreads();

    const int lane = threadIdx.x & 31, warp = threadIdx.x >> 5;
    const int g = lane >> 2, tc = lane & 3;
    const int sg = (g >> 1) + (g & 1)*4;     // sigma(g)
    const int rowA = tile*256 + warp*32;     // tile0 rows [rowA, rowA+16)
    const int rowB = rowA + 16;              // tile1 rows [rowB, rowB+16)

    const float SCL = 0.35355339059f * 1.44269504089f;   // 1/sqrt(8)*log2(e)
    const uint32_t qa0 = __float_as_uint(Ks[(rowA+g  )*12 + tc  ] * SCL);
    const uint32_t qa1 = __float_as_uint(Ks[(rowA+g+8)*12 + tc  ] * SCL);
    const uint32_t qa2 = __float_as_uint(Ks[(rowA+g  )*12 + tc+4] * SCL);
    const uint32_t qa3 = __float_as_uint(Ks[(rowA+g+8)*12 + tc+4] * SCL);
    const uint32_t qb0 = __float_as_uint(Ks[(rowB+g  )*12 + tc  ] * SCL);
    const uint32_t qb1 = __float_as_uint(Ks[(rowB+g+8)*12 + tc  ] * SCL);
    const uint32_t qb2 = __float_as_uint(Ks[(rowB+g  )*12 + tc+4] * SCL);
    const uint32_t qb3 = __float_as_uint(Ks[(rowB+g+8)*12 + tc+4] * SCL);

    float oa0=0.f, oa1=0.f, oa2=0.f, oa3=0.f;   // AV acc tile0
    float ob0=0.f, ob1=0.f, ob2=0.f, ob3=0.f;   // AV acc tile1
    float ra0=0.f, ra1=0.f, rb0=0.f, rb1=0.f;   // rowsum partials

    #pragma unroll 2
    for (int t0 = 0; t0 < SS; t0 += 8) {
        // shared scores B-frag (token-permuted rows; conflict-free banks)
        uint32_t sb0 = __float_as_uint(Ks[(t0+sg)*12 + tc  ]);
        uint32_t sb1 = __float_as_uint(Ks[(t0+sg)*12 + tc+4]);
        float a0=0.f,a1=0.f,a2=0.f,a3=0.f;
        float b0=0.f,b1=0.f,b2=0.f,b3=0.f;
        mma_tf32u(a0,a1,a2,a3, qa0,qa1,qa2,qa3, sb0,sb1);
        mma_tf32u(b0,b1,b2,b3, qb0,qb1,qb2,qb3, sb0,sb1);

        // tile0 exp on MUFU, tile1 exp on FMA pipe (log2 domain)
        float pA0 = ex2a(a0),  pA1 = ex2a(a1),  pA2 = ex2a(a2),  pA3 = ex2a(a3);
        float pB0 = exp2p(b0), pB1 = exp2p(b1), pB2 = exp2p(b2), pB3 = exp2p(b3);
        ra0 += pA0 + pA1;  ra1 += pA2 + pA3;
        rb0 += pB0 + pB1;  rb1 += pB2 + pB3;

        // shared AV B-frag
        uint32_t vb0 = __float_as_uint(Ks[(t0+tc  )*12 + g]);
        uint32_t vb1 = __float_as_uint(Ks[(t0+tc+4)*12 + g]);
        // A-frag = (p0, p2, p1, p3) directly (permuted-token layout)
        mma_tf32u(oa0,oa1,oa2,oa3,
                  __float_as_uint(pA0), __float_as_uint(pA2),
                  __float_as_uint(pA1), __float_as_uint(pA3), vb0, vb1);
        mma_tf32u(ob0,ob1,ob2,ob3,
                  __float_as_uint(pB0), __float_as_uint(pB2),
                  __float_as_uint(pB1), __float_as_uint(pB3), vb0, vb1);
    }

    ra0 += __shfl_xor_sync(0xffffffffu, ra0, 1);
    ra0 += __shfl_xor_sync(0xffffffffu, ra0, 2);
    ra1 += __shfl_xor_sync(0xffffffffu, ra1, 1);
    ra1 += __shfl_xor_sync(0xffffffffu, ra1, 2);
    rb0 += __shfl_xor_sync(0xffffffffu, rb0, 1);
    rb0 += __shfl_xor_sync(0xffffffffu, rb0, 2);
    rb1 += __shfl_xor_sync(0xffffffffu, rb1, 1);
    rb1 += __shfl_xor_sync(0xffffffffu, rb1, 2);
    float ia0 = 1.0f / ra0, ia1 = 1.0f / ra1;
    float ib0 = 1.0f / rb0, ib1 = 1.0f / rb1;

    const int b = bh >> 6, h = bh & (HH-1);
    float* base = g_attn + b*SS*EE + h*DKK + 2*tc;
    *(float2*)(base + (rowA+g   )*EE) = make_float2(oa0*ia0, oa1*ia0);
    *(float2*)(base + (rowA+g+8 )*EE) = make_float2(oa2*ia1, oa3*ia1);
    *(float2*)(base + (rowB+g   )*EE) = make_float2(ob0*ib0, ob1*ib0);
    *(float2*)(base + (rowB+g+8 )*EE) = make_float2(ob2*ib1, ob3*ib1);
}

// =====================================================================
// tf32 tensor-core GEMM: out = A @ W (+bias,+res,relu)
// =====================================================================
template<int KTOT, bool RELU>
__global__ void __launch_bounds__(256) mma_gemm_kernel(
    const float* __restrict__ A, const float* __restrict__ W,
    const float* __restrict__ bias, const float* __restrict__ res,
    float* __restrict__ out, int N)
{
    __shared__ float As[32][36];
    __shared__ float Bs[32][136];

    const int rowbase = blockIdx.y * 32;
    const int colbase = blockIdx.x * 128;
    const int tid  = threadIdx.x;
    const int warp = tid >> 5, lane = tid & 31;
    const int wm = warp >> 2;
    const int wn = warp & 3;
    const int g  = lane >> 2, tc = lane & 3;

    float acc[4][4];
    #pragma unroll
    for (int i = 0; i < 4; i++)
        #pragma unroll
        for (int j = 0; j < 4; j++) acc[i][j] = 0.f;

    const int arow = tid >> 3, ak = (tid & 7) * 4;
    const float* Aptr = A + (rowbase + arow) * KTOT + ak;

    float4 aReg = *(const float4*)(Aptr);
    float4 bReg[4];
    #pragma unroll
    for (int i = 0; i < 4; i++) {
        int lin = tid + i*256;
        int br = lin >> 5, bc = (lin & 31) * 4;
        bReg[i] = *(const float4*)(W + br * N + colbase + bc);
    }

    const int NCHUNK = KTOT / 32;
    #pragma unroll 1
    for (int ch = 0; ch < NCHUNK; ch++) {
        __syncthreads();
        *(float4*)&As[arow][ak] = aReg;
        #pragma unroll
        for (int i = 0; i < 4; i++) {
            int lin = tid + i*256;
            int br = lin >> 5, bc = (lin & 31) * 4;
            *(float4*)&Bs[br][bc] = bReg[i];
        }
        __syncthreads();

        if (ch + 1 < NCHUNK) {
            aReg = *(const float4*)(Aptr + (ch+1)*32);
            #pragma unroll
            for (int i = 0; i < 4; i++) {
                int lin = tid + i*256;
                int br = lin >> 5, bc = (lin & 31) * 4;
                bReg[i] = *(const float4*)(W + ((ch+1)*32 + br) * N + colbase + bc);
            }
        }

        #pragma unroll
        for (int ks = 0; ks < 4; ks++) {
            const int k0 = ks * 8;
            float a0 = As[wm*16 + g    ][k0 + tc];
            float a1 = As[wm*16 + g + 8][k0 + tc];
            float a2 = As[wm*16 + g    ][k0 + tc + 4];
            float a3 = As[wm*16 + g + 8][k0 + tc + 4];
            #pragma unroll
            for (int nt = 0; nt < 4; nt++) {
                int nb = wn*32 + nt*8 + g;
                float b0 = Bs[k0 + tc    ][nb];
                float b1 = Bs[k0 + tc + 4][nb];
                mma_tf32(acc[nt], a0, a1, a2, a3, b0, b1);
            }
        }
    }

    #pragma unroll
    for (int nt = 0; nt < 4; nt++) {
        int col = colbase + wn*32 + nt*8 + 2*tc;
        int r0 = rowbase + wm*16 + g;
        int r1 = r0 + 8;
        float bx = bias[col], by = bias[col+1];
        float2 v0 = make_float2(acc[nt][0] + bx, acc[nt][1] + by);
        float2 v1 = make_float2(acc[nt][2] + bx, acc[nt][3] + by);
        if (res != nullptr) {
            float2 s0 = *(const float2*)(res + r0*N + col);
            float2 s1 = *(const float2*)(res + r1*N + col);
            v0.x += s0.x; v0.y += s0.y;
            v1.x += s1.x; v1.y += s1.y;
        }
        if (RELU) {
            v0.x = fmaxf(v0.x, 0.f); v0.y = fmaxf(v0.y, 0.f);
            v1.x = fmaxf(v1.x, 0.f); v1.y = fmaxf(v1.y, 0.f);
        }
        *(float2*)(out + r0*N + col) = v0;
        *(float2*)(out + r1*N + col) = v1;
    }
}

// =====================================================================
// LN kernels
// =====================================================================
__global__ void __launch_bounds__(128) ln1_cos_kernel(
    const float* __restrict__ pre, const float* __restrict__ w,
    const float* __restrict__ b,   const float* __restrict__ thf)
{
    __shared__ float sS[4], sQ[4];
    const int row = blockIdx.x;
    const int t = threadIdx.x;
    float4 v = ((const float4*)(pre + row*EE))[t];
    float s = v.x + v.y + v.z + v.w;
    float q = v.x*v.x + v.y*v.y + v.z*v.z + v.w*v.w;
    #pragma unroll
    for (int o = 16; o; o >>= 1) {
        s += __shfl_xor_sync(0xffffffffu, s, o);
        q += __shfl_xor_sync(0xffffffffu, q, o);
    }
    if ((t & 31) == 0) { sS[t>>5] = s; sQ[t>>5] = q; }
    __syncthreads();
    s = sS[0] + sS[1] + sS[2] + sS[3];
    q = sQ[0] + sQ[1] + sQ[2] + sQ[3];
    float mu   = s * (1.0f/EE);
    float var  = q * (1.0f/EE) - mu*mu;
    float rstd = rsqrtf(var + 1e-5f);
    float4 lw = ((const float4*)w)[t];
    float4 lb = ((const float4*)b)[t];
    float4 th = ((const float4*)thf)[t];
    float4 x1;
    x1.x = (v.x - mu)*rstd*lw.x + lb.x;
    x1.y = (v.y - mu)*rstd*lw.y + lb.y;
    x1.z = (v.z - mu)*rstd*lw.z + lb.z;
    x1.w = (v.w - mu)*rstd*lw.w + lb.w;
    ((float4*)(g_x1 + row*EE))[t] = x1;
    float4 qf;
    qf.x = __cosf(x1.x)*__cosf(th.x);
    qf.y = __cosf(x1.y)*__cosf(th.y);
    qf.z = __cosf(x1.z)*__cosf(th.z);
    qf.w = __cosf(x1.w)*__cosf(th.w);
    ((float4*)(g_qf + row*EE))[t] = qf;
}

__global__ void __launch_bounds__(128) ln2_kernel(
    const float* __restrict__ pre, const float* __restrict__ w,
    const float* __restrict__ b,   float* __restrict__ out)
{
    __shared__ float sS[4], sQ[4];
    const int row = blockIdx.x;
    const int t = threadIdx.x;
    float4 v = ((const float4*)(pre + row*EE))[t];
    float s = v.x + v.y + v.z + v.w;
    float q = v.x*v.x + v.y*v.y + v.z*v.z + v.w*v.w;
    #pragma unroll
    for (int o = 16; o; o >>= 1) {
        s += __shfl_xor_sync(0xffffffffu, s, o);
        q += __shfl_xor_sync(0xffffffffu, q, o);
    }
    if ((t & 31) == 0) { sS[t>>5] = s; sQ[t>>5] = q; }
    __syncthreads();
    s = sS[0] + sS[1] + sS[2] + sS[3];
    q = sQ[0] + sQ[1] + sQ[2] + sQ[3];
    float mu   = s * (1.0f/EE);
    float var  = q * (1.0f/EE) - mu*mu;
    float rstd = rsqrtf(var + 1e-5f);
    float4 lw = ((const float4*)w)[t];
    float4 lb = ((const float4*)b)[t];
    float4 o4;
    o4.x = (v.x - mu)*rstd*lw.x + lb.x;
    o4.y = (v.y - mu)*rstd*lw.y + lb.y;
    o4.z = (v.z - mu)*rstd*lw.z + lb.z;
    o4.w = (v.w - mu)*rstd*lw.w + lb.w;
    ((float4*)(out + row*EE))[t] = o4;
}

// =====================================================================
extern "C" void kernel_launch(void* const* d_in, const int* in_sizes, int n_in,
                              void* d_out, int out_size) {
    const float* x         = (const float*)d_in[0];
    const float* theta_at  = (const float*)d_in[1];
    const float* w_combine = (const float*)d_in[2];
    const float* b_combine = (const float*)d_in[3];
    const float* theta_ffn = (const float*)d_in[4];
    const float* w1        = (const float*)d_in[5];
    const float* b1        = (const float*)d_in[6];
    const float* w2        = (const float*)d_in[7];
    const float* b2        = (const float*)d_in[8];
    const float* ln1w      = (const float*)d_in[9];
    const float* ln1b      = (const float*)d_in[10];
    const float* ln2w      = (const float*)d_in[11];
    const float* ln2b      = (const float*)d_in[12];
    float* out = (float*)d_out;

    float* d_attn; cudaGetSymbolAddress((void**)&d_attn, g_attn);
    float* d_x1;   cudaGetSymbolAddress((void**)&d_x1,   g_x1);
    float* d_qf;   cudaGetSymbolAddress((void**)&d_qf,   g_qf);
    float* d_hdn;  cudaGetSymbolAddress((void**)&d_hdn,  g_hdn);
    float* d_pre;  cudaGetSymbolAddress((void**)&d_pre,  g_pre);

    qkv_kernel<<<512, 256>>>(x, theta_at);
    attn_mma_kernel<<<512, 256>>>();    // 128 bh x 4 row-tiles (256 rows each)

    mma_gemm_kernel<512, false><<<dim3(4, 64), 256>>>(
        d_attn, w_combine, b_combine, x, d_pre, EE);
    ln1_cos_kernel<<<BS, 128>>>(d_pre, ln1w, ln1b, theta_ffn);

    mma_gemm_kernel<512, true><<<dim3(16, 64), 256>>>(
        d_qf, w1, b1, nullptr, d_hdn, FF);

    mma_gemm_kernel<2048, false><<<dim3(4, 64), 256>>>(
        d_hdn, w2, b2, d_x1, d_pre, EE);
    ln2_kernel<<<BS, 128>>>(d_pre, ln2w, ln2b, out);
}

// round 9
// speedup vs baseline: 1.0188x; 1.0188x over previous
#include <cuda_runtime.h>
#include <math.h>
#include <stdint.h>

#define BB 2
#define SS 1024
#define EE 512
#define HH 64
#define DKK 8
#define FF 2048
#define BS (BB*SS)   // 2048

// ---- scratch (device globals: allocation-free) ----
__device__ float g_q[BB*HH*SS*DKK];   // [B][H][S][8]
__device__ float g_attn[BS*EE];
__device__ float g_x1[BS*EE];
__device__ float g_qf[BS*EE];
__device__ float g_hdn[BS*FF];
__device__ float g_pre[BS*EE];

__device__ __forceinline__ float ex2a(float x) {
    float r; asm("ex2.approx.f32 %0, %1;" : "=f"(r) : "f"(x)); return r;
}
// deg-4 range-reduced exp2 on the FMA pipe (rel err ~4e-5), t in [-4.2, 4.2]
__device__ __forceinline__ float exp2p(float t) {
    float tm = t + 12582912.0f;              // round-to-nearest via magic
    float f  = t - (tm - 12582912.0f);       // f in [-0.5, 0.5]
    float p  = 1.0f + f*(0.69314718f + f*(0.24022652f + f*(0.05550411f
             + f*0.00961813f)));
    return __int_as_float(__float_as_int(p) + (__float_as_int(tm) << 23));
}

// m16n8k8 tf32 mma (HW truncates f32 regs to tf32)
__device__ __forceinline__ void mma_tf32(float* acc, float a0, float a1,
                                         float a2, float a3, float b0, float b1) {
    uint32_t A0 = __float_as_uint(a0), A1 = __float_as_uint(a1);
    uint32_t A2 = __float_as_uint(a2), A3 = __float_as_uint(a3);
    uint32_t B0 = __float_as_uint(b0), B1 = __float_as_uint(b1);
    asm volatile(
        "mma.sync.aligned.m16n8k8.row.col.f32.tf32.tf32.f32 "
        "{%0,%1,%2,%3},{%4,%5,%6,%7},{%8,%9},{%0,%1,%2,%3};"
        : "+f"(acc[0]), "+f"(acc[1]), "+f"(acc[2]), "+f"(acc[3])
        : "r"(A0), "r"(A1), "r"(A2), "r"(A3), "r"(B0), "r"(B1));
}
__device__ __forceinline__ void mma_tf32u(float& c0, float& c1, float& c2, float& c3,
                                          uint32_t A0, uint32_t A1, uint32_t A2, uint32_t A3,
                                          uint32_t B0, uint32_t B1) {
    asm volatile(
        "mma.sync.aligned.m16n8k8.row.col.f32.tf32.tf32.f32 "
        "{%0,%1,%2,%3},{%4,%5,%6,%7},{%8,%9},{%0,%1,%2,%3};"
        : "+f"(c0), "+f"(c1), "+f"(c2), "+f"(c3)
        : "r"(A0), "r"(A1), "r"(A2), "r"(A3), "r"(B0), "r"(B1));
}

// =====================================================================
// K1: ring expvals
// =====================================================================
__global__ void qkv_kernel(const float* __restrict__ x,
                           const float* __restrict__ theta) {
    int i = blockIdx.x * 256 + threadIdx.x;
    int h  = i & (HH-1);
    int bs = i >> 6;
    const float* xp = x + bs*EE + h*DKK;
    float4 xa = *(const float4*)xp;
    float4 xb = *(const float4*)(xp + 4);
    float c0 = __cosf(xa.x + theta[0]);
    float c1 = __cosf(xa.y + theta[1]);
    float c2 = __cosf(xa.z + theta[2]);
    float c3 = __cosf(xa.w + theta[3]);
    float c4 = __cosf(xb.x + theta[4]);
    float c5 = __cosf(xb.y + theta[5]);
    float c6 = __cosf(xb.z + theta[6]);
    float c7 = __cosf(xb.w + theta[7]);
    float o1 = c0*c1;
    float o2 = o1*c2;
    float o3 = o2*c3;
    float o4 = o3*c4;
    float o5 = o4*c5;
    float o6 = o5*c6;
    float o7 = o6*c7;
    float o0 = c1*c2*c3*c4*c5*c6*c7;
    int b = bs >> 10, s = bs & (SS-1);
    float* qp = g_q + (((b*HH + h)*SS) + s)*DKK;
    *(float4*)qp       = make_float4(o0, o1, o2, o3);
    *(float4*)(qp + 4) = make_float4(o4, o5, o6, o7);
}

// =====================================================================
// K2: tensor-core attention, zero-shuffle, dual-strip (16 tokens/iter).
// R6 structure exactly (16 rows/warp, known-good regs/occupancy).
// Single change: strip-B exps moved to the FMA-pipe poly; strip-A stays
// on MUFU. Tests the MUFU-throughput hypothesis without R8's spill confound.
// =====================================================================
__global__ void __launch_bounds__(256, 2) attn_mma_kernel() {
    __shared__ float Ks[SS*12];       // 48 KB, row stride 12
    const int bh   = blockIdx.x >> 3;
    const int tile = blockIdx.x & 7;

    const float* qsrc = g_q + bh*(SS*DKK);
    for (int j = threadIdx.x; j < SS*DKK/4; j += 256) {
        float4 v = ((const float4*)qsrc)[j];
        int t = j >> 1, hf = (j & 1) * 4;
        *(float4*)&Ks[t*12 + hf] = v;
    }
    __syncthreads();

    const int lane = threadIdx.x & 31, warp = threadIdx.x >> 5;
    const int g = lane >> 2, tc = lane & 3;
    const int sg = (g >> 1) + (g & 1)*4;     // sigma(g)
    const int row0 = tile*128 + warp*16;

    const float SCL = 0.35355339059f * 1.44269504089f;   // 1/sqrt(8)*log2(e)
    const uint32_t qa0 = __float_as_uint(Ks[(row0+g  )*12 + tc  ] * SCL);
    const uint32_t qa1 = __float_as_uint(Ks[(row0+g+8)*12 + tc  ] * SCL);
    const uint32_t qa2 = __float_as_uint(Ks[(row0+g  )*12 + tc+4] * SCL);
    const uint32_t qa3 = __float_as_uint(Ks[(row0+g+8)*12 + tc+4] * SCL);

    float oa0=0.f, oa1=0.f, oa2=0.f, oa3=0.f;   // AV acc, even strips
    float ob0=0.f, ob1=0.f, ob2=0.f, ob3=0.f;   // AV acc, odd strips
    float ra0=0.f, ra1=0.f, rb0=0.f, rb1=0.f;   // rowsum partials

    #pragma unroll 2
    for (int t0 = 0; t0 < SS; t0 += 16) {
        const int tA = t0, tB = t0 + 8;
        uint32_t sA0 = __float_as_uint(Ks[(tA+sg)*12 + tc  ]);
        uint32_t sA1 = __float_as_uint(Ks[(tA+sg)*12 + tc+4]);
        uint32_t sB0 = __float_as_uint(Ks[(tB+sg)*12 + tc  ]);
        uint32_t sB1 = __float_as_uint(Ks[(tB+sg)*12 + tc+4]);
        float a0=0.f,a1=0.f,a2=0.f,a3=0.f;
        float b0=0.f,b1=0.f,b2=0.f,b3=0.f;
        mma_tf32u(a0,a1,a2,a3, qa0,qa1,qa2,qa3, sA0,sA1);
        mma_tf32u(b0,b1,b2,b3, qa0,qa1,qa2,qa3, sB0,sB1);

        // strip A exp on MUFU, strip B exp on FMA pipe (log2 domain)
        float pA0 = ex2a(a0),  pA1 = ex2a(a1),  pA2 = ex2a(a2),  pA3 = ex2a(a3);
        float pB0 = exp2p(b0), pB1 = exp2p(b1), pB2 = exp2p(b2), pB3 = exp2p(b3);
        ra0 += pA0 + pA1;  ra1 += pA2 + pA3;
        rb0 += pB0 + pB1;  rb1 += pB2 + pB3;

        uint32_t vA0 = __float_as_uint(Ks[(tA+tc  )*12 + g]);
        uint32_t vA1 = __float_as_uint(Ks[(tA+tc+4)*12 + g]);
        uint32_t vB0 = __float_as_uint(Ks[(tB+tc  )*12 + g]);
        uint32_t vB1 = __float_as_uint(Ks[(tB+tc+4)*12 + g]);
        // A-frag = (p0, p2, p1, p3) directly (permuted-token layout)
        mma_tf32u(oa0,oa1,oa2,oa3,
                  __float_as_uint(pA0), __float_as_uint(pA2),
                  __float_as_uint(pA1), __float_as_uint(pA3), vA0, vA1);
        mma_tf32u(ob0,ob1,ob2,ob3,
                  __float_as_uint(pB0), __float_as_uint(pB2),
                  __float_as_uint(pB1), __float_as_uint(pB3), vB0, vB1);
    }

    float rs0 = ra0 + rb0, rs1 = ra1 + rb1;
    rs0 += __shfl_xor_sync(0xffffffffu, rs0, 1);
    rs0 += __shfl_xor_sync(0xffffffffu, rs0, 2);
    rs1 += __shfl_xor_sync(0xffffffffu, rs1, 1);
    rs1 += __shfl_xor_sync(0xffffffffu, rs1, 2);
    float i0 = 1.0f / rs0, i1 = 1.0f / rs1;

    const int b = bh >> 6, h = bh & (HH-1);
    const int r0 = row0 + g, r1 = r0 + 8;
    float* d0 = g_attn + (b*SS + r0)*EE + h*DKK + 2*tc;
    float* d1 = g_attn + (b*SS + r1)*EE + h*DKK + 2*tc;
    *(float2*)d0 = make_float2((oa0+ob0)*i0, (oa1+ob1)*i0);
    *(float2*)d1 = make_float2((oa2+ob2)*i1, (oa3+ob3)*i1);
}

// =====================================================================
// tf32 tensor-core GEMM: out = A @ W (+bias,+res,relu)
// =====================================================================
template<int KTOT, bool RELU>
__global__ void __launch_bounds__(256) mma_gemm_kernel(
    const float* __restrict__ A, const float* __restrict__ W,
    const float* __restrict__ bias, const float* __restrict__ res,
    float* __restrict__ out, int N)
{
    __shared__ float As[32][36];
    __shared__ float Bs[32][136];

    const int rowbase = blockIdx.y * 32;
    const int colbase = blockIdx.x * 128;
    const int tid  = threadIdx.x;
    const int warp = tid >> 5, lane = tid & 31;
    const int wm = warp >> 2;
    const int wn = warp & 3;
    const int g  = lane >> 2, tc = lane & 3;

    float acc[4][4];
    #pragma unroll
    for (int i = 0; i < 4; i++)
        #pragma unroll
        for (int j = 0; j < 4; j++) acc[i][j] = 0.f;

    const int arow = tid >> 3, ak = (tid & 7) * 4;
    const float* Aptr = A + (rowbase + arow) * KTOT + ak;

    float4 aReg = *(const float4*)(Aptr);
    float4 bReg[4];
    #pragma unroll
    for (int i = 0; i < 4; i++) {
        int lin = tid + i*256;
        int br = lin >> 5, bc = (lin & 31) * 4;
        bReg[i] = *(const float4*)(W + br * N + colbase + bc);
    }

    const int NCHUNK = KTOT / 32;
    #pragma unroll 1
    for (int ch = 0; ch < NCHUNK; ch++) {
        __syncthreads();
        *(float4*)&As[arow][ak] = aReg;
        #pragma unroll
        for (int i = 0; i < 4; i++) {
            int lin = tid + i*256;
            int br = lin >> 5, bc = (lin & 31) * 4;
            *(float4*)&Bs[br][bc] = bReg[i];
        }
        __syncthreads();

        if (ch + 1 < NCHUNK) {
            aReg = *(const float4*)(Aptr + (ch+1)*32);
            #pragma unroll
            for (int i = 0; i < 4; i++) {
                int lin = tid + i*256;
                int br = lin >> 5, bc = (lin & 31) * 4;
                bReg[i] = *(const float4*)(W + ((ch+1)*32 + br) * N + colbase + bc);
            }
        }

        #pragma unroll
        for (int ks = 0; ks < 4; ks++) {
            const int k0 = ks * 8;
            float a0 = As[wm*16 + g    ][k0 + tc];
            float a1 = As[wm*16 + g + 8][k0 + tc];
            float a2 = As[wm*16 + g    ][k0 + tc + 4];
            float a3 = As[wm*16 + g + 8][k0 + tc + 4];
            #pragma unroll
            for (int nt = 0; nt < 4; nt++) {
                int nb = wn*32 + nt*8 + g;
                float b0 = Bs[k0 + tc    ][nb];
                float b1 = Bs[k0 + tc + 4][nb];
                mma_tf32(acc[nt], a0, a1, a2, a3, b0, b1);
            }
        }
    }

    #pragma unroll
    for (int nt = 0; nt < 4; nt++) {
        int col = colbase + wn*32 + nt*8 + 2*tc;
        int r0 = rowbase + wm*16 + g;
        int r1 = r0 + 8;
        float bx = bias[col], by = bias[col+1];
        float2 v0 = make_float2(acc[nt][0] + bx, acc[nt][1] + by);
        float2 v1 = make_float2(acc[nt][2] + bx, acc[nt][3] + by);
        if (res != nullptr) {
            float2 s0 = *(const float2*)(res + r0*N + col);
            float2 s1 = *(const float2*)(res + r1*N + col);
            v0.x += s0.x; v0.y += s0.y;
            v1.x += s1.x; v1.y += s1.y;
        }
        if (RELU) {
            v0.x = fmaxf(v0.x, 0.f); v0.y = fmaxf(v0.y, 0.f);
            v1.x = fmaxf(v1.x, 0.f); v1.y = fmaxf(v1.y, 0.f);
        }
        *(float2*)(out + r0*N + col) = v0;
        *(float2*)(out + r1*N + col) = v1;
    }
}

// =====================================================================
// LN kernels
// =====================================================================
__global__ void __launch_bounds__(128) ln1_cos_kernel(
    const float* __restrict__ pre, const float* __restrict__ w,
    const float* __restrict__ b,   const float* __restrict__ thf)
{
    __shared__ float sS[4], sQ[4];
    const int row = blockIdx.x;
    const int t = threadIdx.x;
    float4 v = ((const float4*)(pre + row*EE))[t];
    float s = v.x + v.y + v.z + v.w;
    float q = v.x*v.x + v.y*v.y + v.z*v.z + v.w*v.w;
    #pragma unroll
    for (int o = 16; o; o >>= 1) {
        s += __shfl_xor_sync(0xffffffffu, s, o);
        q += __shfl_xor_sync(0xffffffffu, q, o);
    }
    if ((t & 31) == 0) { sS[t>>5] = s; sQ[t>>5] = q; }
    __syncthreads();
    s = sS[0] + sS[1] + sS[2] + sS[3];
    q = sQ[0] + sQ[1] + sQ[2] + sQ[3];
    float mu   = s * (1.0f/EE);
    float var  = q * (1.0f/EE) - mu*mu;
    float rstd = rsqrtf(var + 1e-5f);
    float4 lw = ((const float4*)w)[t];
    float4 lb = ((const float4*)b)[t];
    float4 th = ((const float4*)thf)[t];
    float4 x1;
    x1.x = (v.x - mu)*rstd*lw.x + lb.x;
    x1.y = (v.y - mu)*rstd*lw.y + lb.y;
    x1.z = (v.z - mu)*rstd*lw.z + lb.z;
    x1.w = (v.w - mu)*rstd*lw.w + lb.w;
    ((float4*)(g_x1 + row*EE))[t] = x1;
    float4 qf;
    qf.x = __cosf(x1.x)*__cosf(th.x);
    qf.y = __cosf(x1.y)*__cosf(th.y);
    qf.z = __cosf(x1.z)*__cosf(th.z);
    qf.w = __cosf(x1.w)*__cosf(th.w);
    ((float4*)(g_qf + row*EE))[t] = qf;
}

__global__ void __launch_bounds__(128) ln2_kernel(
    const float* __restrict__ pre, const float* __restrict__ w,
    const float* __restrict__ b,   float* __restrict__ out)
{
    __shared__ float sS[4], sQ[4];
    const int row = blockIdx.x;
    const int t = threadIdx.x;
    float4 v = ((const float4*)(pre + row*EE))[t];
    float s = v.x + v.y + v.z + v.w;
    float q = v.x*v.x + v.y*v.y + v.z*v.z + v.w*v.w;
    #pragma unroll
    for (int o = 16; o; o >>= 1) {
        s += __shfl_xor_sync(0xffffffffu, s, o);
        q += __shfl_xor_sync(0xffffffffu, q, o);
    }
    if ((t & 31) == 0) { sS[t>>5] = s; sQ[t>>5] = q; }
    __syncthreads();
    s = sS[0] + sS[1] + sS[2] + sS[3];
    q = sQ[0] + sQ[1] + sQ[2] + sQ[3];
    float mu   = s * (1.0f/EE);
    float var  = q * (1.0f/EE) - mu*mu;
    float rstd = rsqrtf(var + 1e-5f);
    float4 lw = ((const float4*)w)[t];
    float4 lb = ((const float4*)b)[t];
    float4 o4;
    o4.x = (v.x - mu)*rstd*lw.x + lb.x;
    o4.y = (v.y - mu)*rstd*lw.y + lb.y;
    o4.z = (v.z - mu)*rstd*lw.z + lb.z;
    o4.w = (v.w - mu)*rstd*lw.w + lb.w;
    ((float4*)(out + row*EE))[t] = o4;
}

// =====================================================================
extern "C" void kernel_launch(void* const* d_in, const int* in_sizes, int n_in,
                              void* d_out, int out_size) {
    const float* x         = (const float*)d_in[0];
    const float* theta_at  = (const float*)d_in[1];
    const float* w_combine = (const float*)d_in[2];
    const float* b_combine = (const float*)d_in[3];
    const float* theta_ffn = (const float*)d_in[4];
    const float* w1        = (const float*)d_in[5];
    const float* b1        = (const float*)d_in[6];
    const float* w2        = (const float*)d_in[7];
    const float* b2        = (const float*)d_in[8];
    const float* ln1w      = (const float*)d_in[9];
    const float* ln1b      = (const float*)d_in[10];
    const float* ln2w      = (const float*)d_in[11];
    const float* ln2b      = (const float*)d_in[12];
    float* out = (float*)d_out;

    float* d_attn; cudaGetSymbolAddress((void**)&d_attn, g_attn);
    float* d_x1;   cudaGetSymbolAddress((void**)&d_x1,   g_x1);
    float* d_qf;   cudaGetSymbolAddress((void**)&d_qf,   g_qf);
    float* d_hdn;  cudaGetSymbolAddress((void**)&d_hdn,  g_hdn);
    float* d_pre;  cudaGetSymbolAddress((void**)&d_pre,  g_pre);

    qkv_kernel<<<512, 256>>>(x, theta_at);
    attn_mma_kernel<<<1024, 256>>>();   // 128 bh x 8 row-tiles

    mma_gemm_kernel<512, false><<<dim3(4, 64), 256>>>(
        d_attn, w_combine, b_combine, x, d_pre, EE);
    ln1_cos_kernel<<<BS, 128>>>(d_pre, ln1w, ln1b, theta_ffn);

    mma_gemm_kernel<512, true><<<dim3(16, 64), 256>>>(
        d_qf, w1, b1, nullptr, d_hdn, FF);

    mma_gemm_kernel<2048, false><<<dim3(4, 64), 256>>>(
        d_hdn, w2, b2, d_x1, d_pre, EE);
    ln2_kernel<<<BS, 128>>>(d_pre, ln2w, ln2b, out);
}

// round 10
// speedup vs baseline: 1.3300x; 1.3054x over previous
#include <cuda_runtime.h>
#include <cuda_fp16.h>
#include <math.h>
#include <stdint.h>

#define BB 2
#define SS 1024
#define EE 512
#define HH 64
#define DKK 8
#define FF 2048
#define BS (BB*SS)   // 2048

// ---- scratch (device globals: allocation-free) ----
__device__ float g_q[BB*HH*SS*DKK];   // [B][H][S][8]
__device__ float g_attn[BS*EE];
__device__ float g_x1[BS*EE];
__device__ float g_qf[BS*EE];
__device__ float g_hdn[BS*FF];
__device__ float g_pre[BS*EE];

__device__ __forceinline__ float ex2a(float x) {
    float r; asm("ex2.approx.f32 %0, %1;" : "=f"(r) : "f"(x)); return r;
}

// m16n8k8 tf32 mma (attention only)
__device__ __forceinline__ void mma_tf32u(float& c0, float& c1, float& c2, float& c3,
                                          uint32_t A0, uint32_t A1, uint32_t A2, uint32_t A3,
                                          uint32_t B0, uint32_t B1) {
    asm volatile(
        "mma.sync.aligned.m16n8k8.row.col.f32.tf32.tf32.f32 "
        "{%0,%1,%2,%3},{%4,%5,%6,%7},{%8,%9},{%0,%1,%2,%3};"
        : "+f"(c0), "+f"(c1), "+f"(c2), "+f"(c3)
        : "r"(A0), "r"(A1), "r"(A2), "r"(A3), "r"(B0), "r"(B1));
}
// m16n8k16 fp16 mma, f32 accumulate (GEMMs)
__device__ __forceinline__ void mma_f16(float* acc,
                                        uint32_t a0, uint32_t a1, uint32_t a2, uint32_t a3,
                                        uint32_t b0, uint32_t b1) {
    asm volatile(
        "mma.sync.aligned.m16n8k16.row.col.f32.f16.f16.f32 "
        "{%0,%1,%2,%3},{%4,%5,%6,%7},{%8,%9},{%0,%1,%2,%3};"
        : "+f"(acc[0]), "+f"(acc[1]), "+f"(acc[2]), "+f"(acc[3])
        : "r"(a0), "r"(a1), "r"(a2), "r"(a3), "r"(b0), "r"(b1));
}
__device__ __forceinline__ uint32_t pack_h2(float lo, float hi) {
    __half2 h = __floats2half2_rn(lo, hi);
    return *reinterpret_cast<uint32_t*>(&h);
}

// =====================================================================
// K1: ring expvals
// =====================================================================
__global__ void qkv_kernel(const float* __restrict__ x,
                           const float* __restrict__ theta) {
    int i = blockIdx.x * 256 + threadIdx.x;
    int h  = i & (HH-1);
    int bs = i >> 6;
    const float* xp = x + bs*EE + h*DKK;
    float4 xa = *(const float4*)xp;
    float4 xb = *(const float4*)(xp + 4);
    float c0 = __cosf(xa.x + theta[0]);
    float c1 = __cosf(xa.y + theta[1]);
    float c2 = __cosf(xa.z + theta[2]);
    float c3 = __cosf(xa.w + theta[3]);
    float c4 = __cosf(xb.x + theta[4]);
    float c5 = __cosf(xb.y + theta[5]);
    float c6 = __cosf(xb.z + theta[6]);
    float c7 = __cosf(xb.w + theta[7]);
    float o1 = c0*c1;
    float o2 = o1*c2;
    float o3 = o2*c3;
    float o4 = o3*c4;
    float o5 = o4*c5;
    float o6 = o5*c6;
    float o7 = o6*c7;
    float o0 = c1*c2*c3*c4*c5*c6*c7;
    int b = bs >> 10, s = bs & (SS-1);
    float* qp = g_q + (((b*HH + h)*SS) + s)*DKK;
    *(float4*)qp       = make_float4(o0, o1, o2, o3);
    *(float4*)(qp + 4) = make_float4(o4, o5, o6, o7);
}

// =====================================================================
// K2: tensor-core attention (R6 known-best form: dual-strip, all-MUFU exp,
// token-permuted zero-shuffle layout).
// =====================================================================
__global__ void __launch_bounds__(256, 4) attn_mma_kernel() {
    __shared__ float Ks[SS*12];       // 48 KB, row stride 12
    const int bh   = blockIdx.x >> 3;
    const int tile = blockIdx.x & 7;

    const float* qsrc = g_q + bh*(SS*DKK);
    for (int j = threadIdx.x; j < SS*DKK/4; j += 256) {
        float4 v = ((const float4*)qsrc)[j];
        int t = j >> 1, hf = (j & 1) * 4;
        *(float4*)&Ks[t*12 + hf] = v;
    }
    __syncthreads();

    const int lane = threadIdx.x & 31, warp = threadIdx.x >> 5;
    const int g = lane >> 2, tc = lane & 3;
    const int sg = (g >> 1) + (g & 1)*4;     // sigma(g)
    const int row0 = tile*128 + warp*16;

    const float SCL = 0.35355339059f * 1.44269504089f;   // 1/sqrt(8)*log2(e)
    const uint32_t qa0 = __float_as_uint(Ks[(row0+g  )*12 + tc  ] * SCL);
    const uint32_t qa1 = __float_as_uint(Ks[(row0+g+8)*12 + tc  ] * SCL);
    const uint32_t qa2 = __float_as_uint(Ks[(row0+g  )*12 + tc+4] * SCL);
    const uint32_t qa3 = __float_as_uint(Ks[(row0+g+8)*12 + tc+4] * SCL);

    float oa0=0.f, oa1=0.f, oa2=0.f, oa3=0.f;
    float ob0=0.f, ob1=0.f, ob2=0.f, ob3=0.f;
    float ra0=0.f, ra1=0.f, rb0=0.f, rb1=0.f;

    #pragma unroll 2
    for (int t0 = 0; t0 < SS; t0 += 16) {
        const int tA = t0, tB = t0 + 8;
        uint32_t sA0 = __float_as_uint(Ks[(tA+sg)*12 + tc  ]);
        uint32_t sA1 = __float_as_uint(Ks[(tA+sg)*12 + tc+4]);
        uint32_t sB0 = __float_as_uint(Ks[(tB+sg)*12 + tc  ]);
        uint32_t sB1 = __float_as_uint(Ks[(tB+sg)*12 + tc+4]);
        float a0=0.f,a1=0.f,a2=0.f,a3=0.f;
        float b0=0.f,b1=0.f,b2=0.f,b3=0.f;
        mma_tf32u(a0,a1,a2,a3, qa0,qa1,qa2,qa3, sA0,sA1);
        mma_tf32u(b0,b1,b2,b3, qa0,qa1,qa2,qa3, sB0,sB1);

        float pA0 = ex2a(a0), pA1 = ex2a(a1), pA2 = ex2a(a2), pA3 = ex2a(a3);
        float pB0 = ex2a(b0), pB1 = ex2a(b1), pB2 = ex2a(b2), pB3 = ex2a(b3);
        ra0 += pA0 + pA1;  ra1 += pA2 + pA3;
        rb0 += pB0 + pB1;  rb1 += pB2 + pB3;

        uint32_t vA0 = __float_as_uint(Ks[(tA+tc  )*12 + g]);
        uint32_t vA1 = __float_as_uint(Ks[(tA+tc+4)*12 + g]);
        uint32_t vB0 = __float_as_uint(Ks[(tB+tc  )*12 + g]);
        uint32_t vB1 = __float_as_uint(Ks[(tB+tc+4)*12 + g]);
        mma_tf32u(oa0,oa1,oa2,oa3,
                  __float_as_uint(pA0), __float_as_uint(pA2),
                  __float_as_uint(pA1), __float_as_uint(pA3), vA0, vA1);
        mma_tf32u(ob0,ob1,ob2,ob3,
                  __float_as_uint(pB0), __float_as_uint(pB2),
                  __float_as_uint(pB1), __float_as_uint(pB3), vB0, vB1);
    }

    float rs0 = ra0 + rb0, rs1 = ra1 + rb1;
    rs0 += __shfl_xor_sync(0xffffffffu, rs0, 1);
    rs0 += __shfl_xor_sync(0xffffffffu, rs0, 2);
    rs1 += __shfl_xor_sync(0xffffffffu, rs1, 1);
    rs1 += __shfl_xor_sync(0xffffffffu, rs1, 2);
    float i0 = 1.0f / rs0, i1 = 1.0f / rs1;

    const int b = bh >> 6, h = bh & (HH-1);
    const int r0 = row0 + g, r1 = r0 + 8;
    float* d0 = g_attn + (b*SS + r0)*EE + h*DKK + 2*tc;
    float* d1 = g_attn + (b*SS + r1)*EE + h*DKK + 2*tc;
    *(float2*)d0 = make_float2((oa0+ob0)*i0, (oa1+ob1)*i0);
    *(float2*)d1 = make_float2((oa2+ob2)*i1, (oa3+ob3)*i1);
}

// =====================================================================
// fp16 m16n8k16 tensor-core GEMM: out = A @ W (+bias,+res,relu)
// block tile 32x128, 8 warps (2M x 4N), warp tile 16x32.
// Per 32-K chunk: 2 k16 steps x 4 MMAs = 8 MMAs/warp (half of tf32-k8).
// As: [32 rows][40 halves] (stride 40 -> frag banks 20g+tc bijective mod 32)
// Bs: k-pair-packed half2 [16][136] (stride 136 -> banks 8tc+g bijective)
// =====================================================================
template<int KTOT, bool RELU>
__global__ void __launch_bounds__(256) mma_gemm_kernel(
    const float* __restrict__ A, const float* __restrict__ W,
    const float* __restrict__ bias, const float* __restrict__ res,
    float* __restrict__ out, int N)
{
    __shared__ __half As[32][40];
    __shared__ __half2 Bs[16][136];

    const int rowbase = blockIdx.y * 32;
    const int colbase = blockIdx.x * 128;
    const int tid  = threadIdx.x;
    const int warp = tid >> 5, lane = tid & 31;
    const int wm = warp >> 2;
    const int wn = warp & 3;
    const int g  = lane >> 2, tc = lane & 3;

    float acc[4][4];
    #pragma unroll
    for (int i = 0; i < 4; i++)
        #pragma unroll
        for (int j = 0; j < 4; j++) acc[i][j] = 0.f;

    // A staging: thread -> (row, 4 k-elems)
    const int arow = tid >> 3, ak = (tid & 7) * 4;
    const float* Aptr = A + (rowbase + arow) * KTOT + ak;
    // B staging: 4 items; item -> (k-pair kk, 2 cols)
    // lin = tid + i*256 in [0,1024): kk = lin>>6 (0..15), c2 = (lin&63)*2

    float4 aReg = *(const float4*)(Aptr);
    float2 bReg0[4], bReg1[4];
    #pragma unroll
    for (int i = 0; i < 4; i++) {
        int lin = tid + i*256;
        int kk = lin >> 6, c2 = (lin & 63) * 2;
        bReg0[i] = *(const float2*)(W + (2*kk  ) * N + colbase + c2);
        bReg1[i] = *(const float2*)(W + (2*kk+1) * N + colbase + c2);
    }

    const int NCHUNK = KTOT / 32;
    #pragma unroll 1
    for (int ch = 0; ch < NCHUNK; ch++) {
        __syncthreads();
        // stage A as fp16
        {
            uint32_t h0 = pack_h2(aReg.x, aReg.y);
            uint32_t h1 = pack_h2(aReg.z, aReg.w);
            *reinterpret_cast<uint2*>(&As[arow][ak]) = make_uint2(h0, h1);
        }
        // stage B as k-pair-packed fp16
        #pragma unroll
        for (int i = 0; i < 4; i++) {
            int lin = tid + i*256;
            int kk = lin >> 6, c2 = (lin & 63) * 2;
            uint32_t h0 = pack_h2(bReg0[i].x, bReg1[i].x);  // {W[2kk][c], W[2kk+1][c]}
            uint32_t h1 = pack_h2(bReg0[i].y, bReg1[i].y);
            *reinterpret_cast<uint2*>(&Bs[kk][c2]) = make_uint2(h0, h1);
        }
        __syncthreads();

        if (ch + 1 < NCHUNK) {
            aReg = *(const float4*)(Aptr + (ch+1)*32);
            #pragma unroll
            for (int i = 0; i < 4; i++) {
                int lin = tid + i*256;
                int kk = lin >> 6, c2 = (lin & 63) * 2;
                bReg0[i] = *(const float2*)(W + ((ch+1)*32 + 2*kk  ) * N + colbase + c2);
                bReg1[i] = *(const float2*)(W + ((ch+1)*32 + 2*kk+1) * N + colbase + c2);
            }
        }

        #pragma unroll
        for (int s = 0; s < 2; s++) {
            const int kc = s*16 + 2*tc;
            uint32_t a0 = *reinterpret_cast<const uint32_t*>(&As[wm*16 + g    ][kc    ]);
            uint32_t a1 = *reinterpret_cast<const uint32_t*>(&As[wm*16 + g + 8][kc    ]);
            uint32_t a2 = *reinterpret_cast<const uint32_t*>(&As[wm*16 + g    ][kc + 8]);
            uint32_t a3 = *reinterpret_cast<const uint32_t*>(&As[wm*16 + g + 8][kc + 8]);
            #pragma unroll
            for (int nt = 0; nt < 4; nt++) {
                int col = wn*32 + nt*8 + g;
                uint32_t b0 = *reinterpret_cast<const uint32_t*>(&Bs[s*8 + tc    ][col]);
                uint32_t b1 = *reinterpret_cast<const uint32_t*>(&Bs[s*8 + tc + 4][col]);
                mma_f16(acc[nt], a0, a1, a2, a3, b0, b1);
            }
        }
    }

    // epilogue: bias (+residual) (+relu)  — C layout same as k8 path
    #pragma unroll
    for (int nt = 0; nt < 4; nt++) {
        int col = colbase + wn*32 + nt*8 + 2*tc;
        int r0 = rowbase + wm*16 + g;
        int r1 = r0 + 8;
        float bx = bias[col], by = bias[col+1];
        float2 v0 = make_float2(acc[nt][0] + bx, acc[nt][1] + by);
        float2 v1 = make_float2(acc[nt][2] + bx, acc[nt][3] + by);
        if (res != nullptr) {
            float2 s0 = *(const float2*)(res + r0*N + col);
            float2 s1 = *(const float2*)(res + r1*N + col);
            v0.x += s0.x; v0.y += s0.y;
            v1.x += s1.x; v1.y += s1.y;
        }
        if (RELU) {
            v0.x = fmaxf(v0.x, 0.f); v0.y = fmaxf(v0.y, 0.f);
            v1.x = fmaxf(v1.x, 0.f); v1.y = fmaxf(v1.y, 0.f);
        }
        *(float2*)(out + r0*N + col) = v0;
        *(float2*)(out + r1*N + col) = v1;
    }
}

// =====================================================================
// LN kernels
// =====================================================================
__global__ void __launch_bounds__(128) ln1_cos_kernel(
    const float* __restrict__ pre, const float* __restrict__ w,
    const float* __restrict__ b,   const float* __restrict__ thf)
{
    __shared__ float sS[4], sQ[4];
    const int row = blockIdx.x;
    const int t = threadIdx.x;
    float4 v = ((const float4*)(pre + row*EE))[t];
    float s = v.x + v.y + v.z + v.w;
    float q = v.x*v.x + v.y*v.y + v.z*v.z + v.w*v.w;
    #pragma unroll
    for (int o = 16; o; o >>= 1) {
        s += __shfl_xor_sync(0xffffffffu, s, o);
        q += __shfl_xor_sync(0xffffffffu, q, o);
    }
    if ((t & 31) == 0) { sS[t>>5] = s; sQ[t>>5] = q; }
    __syncthreads();
    s = sS[0] + sS[1] + sS[2] + sS[3];
    q = sQ[0] + sQ[1] + sQ[2] + sQ[3];
    float mu   = s * (1.0f/EE);
    float var  = q * (1.0f/EE) - mu*mu;
    float rstd = rsqrtf(var + 1e-5f);
    float4 lw = ((const float4*)w)[t];
    float4 lb = ((const float4*)b)[t];
    float4 th = ((const float4*)thf)[t];
    float4 x1;
    x1.x = (v.x - mu)*rstd*lw.x + lb.x;
    x1.y = (v.y - mu)*rstd*lw.y + lb.y;
    x1.z = (v.z - mu)*rstd*lw.z + lb.z;
    x1.w = (v.w - mu)*rstd*lw.w + lb.w;
    ((float4*)(g_x1 + row*EE))[t] = x1;
    float4 qf;
    qf.x = __cosf(x1.x)*__cosf(th.x);
    qf.y = __cosf(x1.y)*__cosf(th.y);
    qf.z = __cosf(x1.z)*__cosf(th.z);
    qf.w = __cosf(x1.w)*__cosf(th.w);
    ((float4*)(g_qf + row*EE))[t] = qf;
}

__global__ void __launch_bounds__(128) ln2_kernel(
    const float* __restrict__ pre, const float* __restrict__ w,
    const float* __restrict__ b,   float* __restrict__ out)
{
    __shared__ float sS[4], sQ[4];
    const int row = blockIdx.x;
    const int t = threadIdx.x;
    float4 v = ((const float4*)(pre + row*EE))[t];
    float s = v.x + v.y + v.z + v.w;
    float q = v.x*v.x + v.y*v.y + v.z*v.z + v.w*v.w;
    #pragma unroll
    for (int o = 16; o; o >>= 1) {
        s += __shfl_xor_sync(0xffffffffu, s, o);
        q += __shfl_xor_sync(0xffffffffu, q, o);
    }
    if ((t & 31) == 0) { sS[t>>5] = s; sQ[t>>5] = q; }
    __syncthreads();
    s = sS[0] + sS[1] + sS[2] + sS[3];
    q = sQ[0] + sQ[1] + sQ[2] + sQ[3];
    float mu   = s * (1.0f/EE);
    float var  = q * (1.0f/EE) - mu*mu;
    float rstd = rsqrtf(var + 1e-5f);
    float4 lw = ((const float4*)w)[t];
    float4 lb = ((const float4*)b)[t];
    float4 o4;
    o4.x = (v.x - mu)*rstd*lw.x + lb.x;
    o4.y = (v.y - mu)*rstd*lw.y + lb.y;
    o4.z = (v.z - mu)*rstd*lw.z + lb.z;
    o4.w = (v.w - mu)*rstd*lw.w + lb.w;
    ((float4*)(out + row*EE))[t] = o4;
}

// =====================================================================
extern "C" void kernel_launch(void* const* d_in, const int* in_sizes, int n_in,
                              void* d_out, int out_size) {
    const float* x         = (const float*)d_in[0];
    const float* theta_at  = (const float*)d_in[1];
    const float* w_combine = (const float*)d_in[2];
    const float* b_combine = (const float*)d_in[3];
    const float* theta_ffn = (const float*)d_in[4];
    const float* w1        = (const float*)d_in[5];
    const float* b1        = (const float*)d_in[6];
    const float* w2        = (const float*)d_in[7];
    const float* b2        = (const float*)d_in[8];
    const float* ln1w      = (const float*)d_in[9];
    const float* ln1b      = (const float*)d_in[10];
    const float* ln2w      = (const float*)d_in[11];
    const float* ln2b      = (const float*)d_in[12];
    float* out = (float*)d_out;

    float* d_attn; cudaGetSymbolAddress((void**)&d_attn, g_attn);
    float* d_x1;   cudaGetSymbolAddress((void**)&d_x1,   g_x1);
    float* d_qf;   cudaGetSymbolAddress((void**)&d_qf,   g_qf);
    float* d_hdn;  cudaGetSymbolAddress((void**)&d_hdn,  g_hdn);
    float* d_pre;  cudaGetSymbolAddress((void**)&d_pre,  g_pre);

    qkv_kernel<<<512, 256>>>(x, theta_at);
    attn_mma_kernel<<<1024, 256>>>();

    mma_gemm_kernel<512, false><<<dim3(4, 64), 256>>>(
        d_attn, w_combine, b_combine, x, d_pre, EE);
    ln1_cos_kernel<<<BS, 128>>>(d_pre, ln1w, ln1b, theta_ffn);

    mma_gemm_kernel<512, true><<<dim3(16, 64), 256>>>(
        d_qf, w1, b1, nullptr, d_hdn, FF);

    mma_gemm_kernel<2048, false><<<dim3(4, 64), 256>>>(
        d_hdn, w2, b2, d_x1, d_pre, EE);
    ln2_kernel<<<BS, 128>>>(d_pre, ln2w, ln2b, out);
}